// round 13
// baseline (speedup 1.0000x reference)
#include <cuda_runtime.h>
#include <cuda_bf16.h>

#define S_LEN 512
#define B_DIM 256
#define Z_DIM 64

// ---- packed f32x2 helpers (full fp32 precision, 2 MACs per instruction) ----
__device__ __forceinline__ unsigned long long pack2(float lo, float hi) {
    unsigned long long r;
    asm("mov.b64 %0, {%1, %2};" : "=l"(r) : "f"(lo), "f"(hi));
    return r;
}
__device__ __forceinline__ unsigned long long fma2(unsigned long long a,
                                                   unsigned long long b,
                                                   unsigned long long c) {
    unsigned long long d;
    asm("fma.rn.f32x2 %0, %1, %2, %3;" : "=l"(d) : "l"(a), "l"(b), "l"(c));
    return d;
}
__device__ __forceinline__ unsigned long long add2(unsigned long long a,
                                                   unsigned long long b) {
    unsigned long long d;
    asm("add.rn.f32x2 %0, %1, %2;" : "=l"(d) : "l"(a), "l"(b));
    return d;
}
__device__ __forceinline__ float hsum2(unsigned long long v) {
    float lo, hi;
    asm("mov.b64 {%0, %1}, %2;" : "=f"(lo), "=f"(hi) : "l"(v));
    return lo + hi;
}

// FFMA2 dot: 64-float smem vector (16 LDS.128) vs 32 packed T pairs (TP) in
// regs. 4 independent f32x2 chains, depth 8 (caps accumulator registers).
#define DOT64(VR, TP, result)                                                  \
    {                                                                          \
        const ulonglong2* p2 = reinterpret_cast<const ulonglong2*>(VR);        \
        unsigned long long s0 = 0, s1 = 0, s2 = 0, s3 = 0;                     \
        _Pragma("unroll")                                                      \
        for (int q = 0; q < 8; q++) {                                          \
            ulonglong2 u = p2[2 * q + 0];                                      \
            ulonglong2 w = p2[2 * q + 1];                                      \
            s0 = fma2(u.x, TP[4 * q + 0], s0);                                 \
            s1 = fma2(u.y, TP[4 * q + 1], s1);                                 \
            s2 = fma2(w.x, TP[4 * q + 2], s2);                                 \
            s3 = fma2(w.y, TP[4 * q + 3], s3);                                 \
        }                                                                      \
        result = hsum2(add2(add2(s0, s1), add2(s2, s3)));                      \
    }

// ---------------------------------------------------------------------------
// Paired forward+backward per CTA. 256 CTAs x 64 threads; CTA b runs BOTH
// recursions of batch b. Per step each thread computes TWO independent dots
// (fwd row z, bwd col z) -> intra-warp ILP fills the latency that R12's
// single-chain warps exposed. One barrier per step serves both exchanges.
// Output STGs + emission prefetches live in the post-barrier shadow.
//   fwd step t:  reads vf[(t-1)&1], writes vf[t&1]
//   bwd step t:  reads vb[(t+1)&1], writes vb[t&1]
// ---------------------------------------------------------------------------
__global__ __launch_bounds__(Z_DIM, 1)
void hmm_fb_kernel(const int* __restrict__ inp,      // [S, B]
                   const float* __restrict__ T,      // [Z, Z]
                   const float* __restrict__ pi,     // [Z]
                   const float* __restrict__ emit,   // [X, Z]
                   float* __restrict__ alpha,        // [S, B, Z]
                   float* __restrict__ beta)         // [S, B, Z]
{
    const int b = blockIdx.x;
    const int z = threadIdx.x;

    __shared__ __align__(16) float vf[2][Z_DIM];
    __shared__ __align__(16) float vb[2][Z_DIM];
    __shared__ int x_sh[S_LEN];

    #pragma unroll
    for (int t = z; t < S_LEN; t += Z_DIM) x_sh[t] = inp[t * B_DIM + b];

    // Fwd: row z of T, packed pairwise. Bwd: column z of T, packed pairwise.
    unsigned long long Tpf[Z_DIM / 2], Tpb[Z_DIM / 2];
    #pragma unroll
    for (int k = 0; k < Z_DIM; k += 4) {
        float4 v = *reinterpret_cast<const float4*>(&T[z * Z_DIM + k]);
        Tpf[k / 2]     = pack2(v.x, v.y);
        Tpf[k / 2 + 1] = pack2(v.z, v.w);
    }
    #pragma unroll
    for (int k = 0; k < Z_DIM; k += 2) {
        Tpb[k / 2] = pack2(T[k * Z_DIM + z], T[(k + 1) * Z_DIM + z]);
    }
    __syncthreads();            // x_sh visible before any use

    float* aw = alpha + (size_t)b * Z_DIM;
    float* bw = beta  + (size_t)b * Z_DIM;

    // ---- init: fwd t=0, bwd t=511 ----
    float a0 = emit[x_sh[0] * Z_DIM + z] * pi[z];
    vf[0][z] = a0;
    float  f_pend = a0;
    size_t f_pofs = z;                                       // alpha[0]
    vb[1][z] = emit[x_sh[S_LEN - 1] * Z_DIM + z];            // c[511]
    float  b_pend = 1.0f;
    size_t b_pofs = (size_t)(S_LEN - 1) * B_DIM * Z_DIM + z; // beta[511]
    float Efo = emit[x_sh[1] * Z_DIM + z];     // fwd e, odd steps  (t=1)
    float Efe = emit[x_sh[2] * Z_DIM + z];     // fwd e, even steps (t=2)
    float Ebe = emit[x_sh[S_LEN - 2] * Z_DIM + z];  // bwd e, even steps (510)
    float Ebo = emit[x_sh[S_LEN - 3] * Z_DIM + z];  // bwd e, odd steps  (509)
    __syncthreads();

#define STEP(tf, tb, FR, FW, BR, BW, EF, EB)                                   \
    {                                                                          \
        float df; DOT64(FR, Tpf, df);                                          \
        float db; DOT64(BR, Tpb, db);                                          \
        float nf = (EF) * df;                                                  \
        (FW)[z] = nf;                                                          \
        (BW)[z] = (EB) * db;                                                   \
        __syncthreads();                                                       \
        /* post-barrier shadow: delayed STGs + emission prefetches */          \
        __stcs(&aw[f_pofs], f_pend);                                           \
        __stcs(&bw[b_pofs], b_pend);                                           \
        f_pend = nf; f_pofs = (size_t)(tf) * B_DIM * Z_DIM + z;                \
        b_pend = db; b_pofs = (size_t)(tb) * B_DIM * Z_DIM + z;                \
        EF = emit[x_sh[((tf) + 2 < S_LEN) ? (tf) + 2 : S_LEN - 1] * Z_DIM + z];\
        EB = emit[x_sh[((tb) >= 2) ? (tb) - 2 : 0] * Z_DIM + z];               \
    }

    // k = 1..510 paired: A slot (tf odd, tb even), B slot (tf even, tb odd)
    for (int k = 1; k <= S_LEN - 3; k += 2) {
        STEP(k,     S_LEN - 1 - k, vf[0], vf[1], vb[1], vb[0], Efo, Ebe);
        STEP(k + 1, S_LEN - 2 - k, vf[1], vf[0], vb[0], vb[1], Efe, Ebo);
    }

    // Tail: fwd t=511 (reads vf[0], e=Efo holds e[511]); bwd t=0 (beta only,
    // reads vb[1]).
    {
        float df; DOT64(vf[0], Tpf, df);
        float db; DOT64(vb[1], Tpb, db);
        float nf = Efo * df;
        __stcs(&aw[f_pofs], f_pend);
        __stcs(&bw[b_pofs], b_pend);
        __stcs(&aw[(size_t)(S_LEN - 1) * B_DIM * Z_DIM + z], nf);
        __stcs(&bw[z], db);
    }
#undef STEP
}

// ---------------------------------------------------------------------------
// Posterior: post = alpha*beta / sum_z(alpha*beta). Streaming, HBM-bound.
// ---------------------------------------------------------------------------
__global__ __launch_bounds__(256)
void hmm_post_kernel(const float* __restrict__ alpha,
                     const float* __restrict__ beta,
                     float* __restrict__ post)
{
    const int gid = blockIdx.x * blockDim.x + threadIdx.x;
    const int row = gid >> 4;
    const int sub = gid & 15;

    const size_t off = (size_t)row * Z_DIM + sub * 4;
    float4 av = __ldcs(reinterpret_cast<const float4*>(alpha + off));
    float4 bv = __ldcs(reinterpret_cast<const float4*>(beta  + off));

    float4 ab;
    ab.x = av.x * bv.x; ab.y = av.y * bv.y;
    ab.z = av.z * bv.z; ab.w = av.w * bv.w;

    float sm = (ab.x + ab.y) + (ab.z + ab.w);
    #pragma unroll
    for (int o = 8; o > 0; o >>= 1) sm += __shfl_xor_sync(0xffffffffu, sm, o);

    float inv = 1.0f / sm;
    float4 p;
    p.x = ab.x * inv; p.y = ab.y * inv; p.z = ab.z * inv; p.w = ab.w * inv;
    __stcs(reinterpret_cast<float4*>(post + off), p);
}

extern "C" void kernel_launch(void* const* d_in, const int* in_sizes, int n_in,
                              void* d_out, int out_size)
{
    const int*   inp  = (const int*)  d_in[0];   // [512, 256] int32
    const float* T    = (const float*)d_in[1];   // [64, 64]
    const float* pi   = (const float*)d_in[2];   // [64]
    const float* emit = (const float*)d_in[3];   // [10000, 64]

    float* out   = (float*)d_out;
    const size_t N = (size_t)S_LEN * B_DIM * Z_DIM;
    float* alpha = out;
    float* beta  = out + N;
    float* post  = out + 2 * N;

    hmm_fb_kernel<<<B_DIM, Z_DIM>>>(inp, T, pi, emit, alpha, beta);

    const int rows = S_LEN * B_DIM;             // 131072
    hmm_post_kernel<<<rows * 16 / 256, 256>>>(alpha, beta, post);
}